// round 2
// baseline (speedup 1.0000x reference)
#include <cuda_runtime.h>
#include <math.h>

#define HEADS   8
#define DIMV    384
#define HD      48
#define ADLAV   343
#define HWD     14
#define NTOK    2744
#define BATCH   8
#define SCALEV  0.14433756729740645f   // 48^-0.5

#define BN_TOT  (BATCH * NTOK)          // 21952

// ---------------- scratch (static device allocations; no cudaMalloc) --------
__device__ float g_q[BATCH * NTOK * DIMV];                 // 8.43M
__device__ float g_kv[BATCH * NTOK * 2 * DIMV];            // 16.86M
__device__ float g_adla[BATCH * ADLAV * DIMV];             // 1.05M
__device__ float g_bias1[HEADS * ADLAV * NTOK];            // 7.53M
__device__ float g_bias2[HEADS * ADLAV * NTOK];            // 7.53M
__device__ float g_logits[BATCH * HEADS * ADLAV * NTOK];   // 60.2M (241MB) reused
__device__ float g_adlav[BATCH * HEADS * ADLAV * HD];      // 1.05M
__device__ float g_attnout[BATCH * NTOK * DIMV];           // 8.43M

// ---------------- generic strided batched SGEMM ------------------------------
// C[m,n] = alpha * sum_k A[m,k]*B[k,n]  (+ bias[m,n] if bias != null)
// batch index z decomposes to b = z/8, h = z%8 with separate strides.
__global__ void sgemm(int M, int N, int K,
    const float* __restrict__ A, long long rsA, long long csA, long long bAb, long long bAh,
    const float* __restrict__ B, long long rsB, long long csB, long long bBb, long long bBh,
    float* __restrict__ C, long long rsC, long long csC, long long bCb, long long bCh,
    const float* __restrict__ Bi, long long rsBi, long long csBi, long long bBih,
    float alpha)
{
    __shared__ float As[16][64];
    __shared__ float Bs[16][64];
    int z  = blockIdx.z;
    int bb = z >> 3;
    int hh = z & 7;
    const float* Ab = A + (long long)bb * bAb + (long long)hh * bAh;
    const float* Bb = B + (long long)bb * bBb + (long long)hh * bBh;
    float*       Cb = C + (long long)bb * bCb + (long long)hh * bCh;
    const float* Bib = Bi ? (Bi + (long long)hh * bBih) : nullptr;

    int m0 = blockIdx.y * 64;
    int n0 = blockIdx.x * 64;
    int tid = threadIdx.x;
    int tx = tid & 15, ty = tid >> 4;

    float acc[4][4] = {};
    for (int k0 = 0; k0 < K; k0 += 16) {
        #pragma unroll
        for (int l = 0; l < 4; l++) {
            int idx = tid + l * 256;
            int kk = idx >> 6;
            int mm = idx & 63;
            int m = m0 + mm, k = k0 + kk;
            As[kk][mm] = (m < M && k < K)
                ? Ab[(long long)m * rsA + (long long)k * csA] : 0.f;
            int n = n0 + mm;
            Bs[kk][mm] = (n < N && k < K)
                ? Bb[(long long)k * rsB + (long long)n * csB] : 0.f;
        }
        __syncthreads();
        #pragma unroll
        for (int kk = 0; kk < 16; kk++) {
            float ra[4], rb[4];
            #pragma unroll
            for (int i = 0; i < 4; i++) ra[i] = As[kk][ty * 4 + i];
            #pragma unroll
            for (int j = 0; j < 4; j++) rb[j] = Bs[kk][tx * 4 + j];
            #pragma unroll
            for (int i = 0; i < 4; i++)
                #pragma unroll
                for (int j = 0; j < 4; j++)
                    acc[i][j] = fmaf(ra[i], rb[j], acc[i][j]);
        }
        __syncthreads();
    }
    #pragma unroll
    for (int i = 0; i < 4; i++) {
        int m = m0 + ty * 4 + i;
        if (m >= M) continue;
        #pragma unroll
        for (int j = 0; j < 4; j++) {
            int n = n0 + tx * 4 + j;
            if (n >= N) continue;
            float v = alpha * acc[i][j];
            if (Bib) v += Bib[(long long)m * rsBi + (long long)n * csBi];
            Cb[(long long)m * rsC + (long long)n * csC] = v;
        }
    }
}

// ---------------- pooling: adla[b,a,c] = mean over 2x2x2 of q ---------------
__global__ void pool_kernel(const float* __restrict__ q, float* __restrict__ adla)
{
    long long t = (long long)blockIdx.x * blockDim.x + threadIdx.x;
    if (t >= (long long)BATCH * ADLAV * DIMV) return;
    int c = (int)(t % DIMV);
    int a = (int)((t / DIMV) % ADLAV);
    int b = (int)(t / ((long long)DIMV * ADLAV));
    int p0 = a / 49, p1 = (a / 7) % 7, p2 = a % 7;
    float s = 0.f;
    #pragma unroll
    for (int r0 = 0; r0 < 2; r0++)
        #pragma unroll
        for (int r1 = 0; r1 < 2; r1++)
            #pragma unroll
            for (int r2 = 0; r2 < 2; r2++) {
                int i = p0 * 2 + r0, j = p1 * 2 + r1, k = p2 * 2 + r2;
                int n = (i * HWD + j) * HWD + k;
                s += q[((long long)b * NTOK + n) * DIMV + c];
            }
    adla[t] = s * 0.125f;
}

// ---------------- trilinear upsample weights (7 -> 14) ----------------------
__device__ __forceinline__ void lin_w(int o, int& x0, int& x1, float& w)
{
    float x = 0.5f * (float)o - 0.25f;
    x = fminf(fmaxf(x, 0.f), 6.f);
    x0 = (int)floorf(x);
    if (x0 > 6) x0 = 6;
    x1 = min(x0 + 1, 6);
    w = x - (float)x0;
}

__device__ __forceinline__ float interp8(const float* __restrict__ t,
    int i0, int i1, float wi, int j0, int j1, float wj, int k0, int k1, float wk)
{
    float c00 = (1.f - wk) * t[(i0 * 7 + j0) * 7 + k0] + wk * t[(i0 * 7 + j0) * 7 + k1];
    float c01 = (1.f - wk) * t[(i0 * 7 + j1) * 7 + k0] + wk * t[(i0 * 7 + j1) * 7 + k1];
    float c10 = (1.f - wk) * t[(i1 * 7 + j0) * 7 + k0] + wk * t[(i1 * 7 + j0) * 7 + k1];
    float c11 = (1.f - wk) * t[(i1 * 7 + j1) * 7 + k0] + wk * t[(i1 * 7 + j1) * 7 + k1];
    float c0 = (1.f - wj) * c00 + wj * c01;
    float c1 = (1.f - wj) * c10 + wj * c11;
    return (1.f - wi) * c0 + wi * c1;
}

// bias1[h,a,n] = interp(an_bias)[h,a,n] + ah[h,a,i] + aw[h,a,j] + ad[h,a,k]
// bias2[h,a,n] = interp(na_bias)[h,a,n] + ha[h,i,a] + wa[h,j,a] + da[h,k,a]
__global__ void biasprep(const float* __restrict__ an, const float* __restrict__ na,
                         const float* __restrict__ ah, const float* __restrict__ aw,
                         const float* __restrict__ ad, const float* __restrict__ ha,
                         const float* __restrict__ wa, const float* __restrict__ da,
                         float* __restrict__ b1, float* __restrict__ b2)
{
    long long t = (long long)blockIdx.x * blockDim.x + threadIdx.x;
    if (t >= (long long)HEADS * ADLAV * NTOK) return;
    int n = (int)(t % NTOK);
    int a = (int)((t / NTOK) % ADLAV);
    int h = (int)(t / ((long long)NTOK * ADLAV));
    int i = n / (HWD * HWD), j = (n / HWD) % HWD, k = n % HWD;
    int i0, i1, j0, j1, k0, k1;
    float wi, wj, wk;
    lin_w(i, i0, i1, wi);
    lin_w(j, j0, j1, wj);
    lin_w(k, k0, k1, wk);
    long long hao = ((long long)h * ADLAV + a);
    const float* anb = an + hao * 343;
    const float* nab = na + hao * 343;
    float v1 = interp8(anb, i0, i1, wi, j0, j1, wj, k0, k1, wk);
    float v2 = interp8(nab, i0, i1, wi, j0, j1, wj, k0, k1, wk);
    v1 += ah[hao * HWD + i] + aw[hao * HWD + j] + ad[hao * HWD + k];
    v2 += ha[((long long)h * HWD + i) * ADLAV + a]
        + wa[((long long)h * HWD + j) * ADLAV + a]
        + da[((long long)h * HWD + k) * ADLAV + a];
    b1[t] = v1;
    b2[t] = v2;
}

// ---------------- row softmax (in place) ------------------------------------
__global__ void softmax_rows(float* __restrict__ buf, int rowLen)
{
    float* p = buf + (long long)blockIdx.x * rowLen;
    __shared__ float red[128];
    int tid = threadIdx.x;
    float m = -1e30f;
    for (int i = tid; i < rowLen; i += 128) m = fmaxf(m, p[i]);
    red[tid] = m; __syncthreads();
    for (int s = 64; s > 0; s >>= 1) { if (tid < s) red[tid] = fmaxf(red[tid], red[tid + s]); __syncthreads(); }
    m = red[0]; __syncthreads();
    float sum = 0.f;
    for (int i = tid; i < rowLen; i += 128) {
        float e = __expf(p[i] - m);
        p[i] = e;
        sum += e;
    }
    red[tid] = sum; __syncthreads();
    for (int s = 64; s > 0; s >>= 1) { if (tid < s) red[tid] += red[tid + s]; __syncthreads(); }
    float inv = 1.f / red[0];
    for (int i = tid; i < rowLen; i += 128) p[i] *= inv;
}

// ---------------- depthwise 3x3x3 conv (SAME), add into out -----------------
__global__ void dwc_add(const float* __restrict__ kv, const float* __restrict__ w,
                        const float* __restrict__ bvec, float* __restrict__ out)
{
    long long t = (long long)blockIdx.x * blockDim.x + threadIdx.x;
    if (t >= (long long)BATCH * NTOK * DIMV) return;
    int c = (int)(t % DIMV);
    int n = (int)((t / DIMV) % NTOK);
    int b = (int)(t / ((long long)DIMV * NTOK));
    int i = n / (HWD * HWD), j = (n / HWD) % HWD, k = n % HWD;
    float acc = bvec[c];
    const float* wc = w + (long long)c * 27;
    #pragma unroll
    for (int di = -1; di <= 1; di++) {
        int ii = i + di;
        if (ii < 0 || ii >= HWD) continue;
        #pragma unroll
        for (int dj = -1; dj <= 1; dj++) {
            int jj = j + dj;
            if (jj < 0 || jj >= HWD) continue;
            #pragma unroll
            for (int dk = -1; dk <= 1; dk++) {
                int kk = k + dk;
                if (kk < 0 || kk >= HWD) continue;
                int nn = (ii * HWD + jj) * HWD + kk;
                acc += kv[((long long)b * NTOK + nn) * (2 * DIMV) + DIMV + c]
                     * wc[(di + 1) * 9 + (dj + 1) * 3 + (dk + 1)];
            }
        }
    }
    out[t] += acc;
}

// ---------------- host launcher ---------------------------------------------
static inline dim3 g2d(int M, int N, int Z) {
    return dim3((unsigned)((N + 63) / 64), (unsigned)((M + 63) / 64), (unsigned)Z);
}

extern "C" void kernel_launch(void* const* d_in, const int* in_sizes, int n_in,
                              void* d_out, int out_size)
{
    const float* x     = (const float*)d_in[0];
    const float* Wq    = (const float*)d_in[1];
    const float* Wkv   = (const float*)d_in[2];
    const float* Wproj = (const float*)d_in[3];
    const float* bproj = (const float*)d_in[4];
    const float* dwcw  = (const float*)d_in[5];
    const float* dwcb  = (const float*)d_in[6];
    const float* an    = (const float*)d_in[7];
    const float* na    = (const float*)d_in[8];
    const float* ah    = (const float*)d_in[9];
    const float* aw    = (const float*)d_in[10];
    const float* ad    = (const float*)d_in[11];
    const float* ha    = (const float*)d_in[12];
    const float* wa    = (const float*)d_in[13];
    const float* da    = (const float*)d_in[14];
    float* out = (float*)d_out;

    void *pq, *pkv, *padla, *pb1, *pb2, *plog, *pav, *pao;
    cudaGetSymbolAddress(&pq, g_q);
    cudaGetSymbolAddress(&pkv, g_kv);
    cudaGetSymbolAddress(&padla, g_adla);
    cudaGetSymbolAddress(&pb1, g_bias1);
    cudaGetSymbolAddress(&pb2, g_bias2);
    cudaGetSymbolAddress(&plog, g_logits);
    cudaGetSymbolAddress(&pav, g_adlav);
    cudaGetSymbolAddress(&pao, g_attnout);
    float* q    = (float*)pq;
    float* kv   = (float*)pkv;
    float* adla = (float*)padla;
    float* b1   = (float*)pb1;
    float* b2   = (float*)pb2;
    float* lg   = (float*)plog;
    float* av   = (float*)pav;
    float* ao   = (float*)pao;

    // 1. q = x @ Wq         [21952,384] x [384,384]
    sgemm<<<g2d(BN_TOT, DIMV, 1), 256>>>(BN_TOT, DIMV, DIMV,
        x,  DIMV, 1, 0, 0,
        Wq, DIMV, 1, 0, 0,
        q,  DIMV, 1, 0, 0,
        nullptr, 0, 0, 0, 1.f);

    // 2. kv = x @ Wkv       [21952,768]
    sgemm<<<g2d(BN_TOT, 2 * DIMV, 1), 256>>>(BN_TOT, 2 * DIMV, DIMV,
        x,   DIMV,    1, 0, 0,
        Wkv, 2 * DIMV, 1, 0, 0,
        kv,  2 * DIMV, 1, 0, 0,
        nullptr, 0, 0, 0, 1.f);

    // 3. adla pooling
    {
        long long tot = (long long)BATCH * ADLAV * DIMV;
        pool_kernel<<<(unsigned)((tot + 255) / 256), 256>>>(q, adla);
    }

    // 4. bias tables
    {
        long long tot = (long long)HEADS * ADLAV * NTOK;
        biasprep<<<(unsigned)((tot + 255) / 256), 256>>>(an, na, ah, aw, ad, ha, wa, da, b1, b2);
    }

    // 5. attn1 logits: [b,h] batched: [343,48] @ [48,2744] * SCALE + bias1
    sgemm<<<g2d(ADLAV, NTOK, BATCH * HEADS), 256>>>(ADLAV, NTOK, HD,
        adla, DIMV, 1, (long long)ADLAV * DIMV, HD,
        kv,   1, 2 * DIMV, (long long)NTOK * 2 * DIMV, HD,
        lg,   NTOK, 1, (long long)HEADS * ADLAV * NTOK, (long long)ADLAV * NTOK,
        b1,   NTOK, 1, (long long)ADLAV * NTOK,
        SCALEV);

    // 6. softmax rows over n (2744)
    softmax_rows<<<BATCH * HEADS * ADLAV, 128>>>(lg, NTOK);

    // 7. adla_v = P1 @ V : [343,2744] @ [2744,48]
    sgemm<<<g2d(ADLAV, HD, BATCH * HEADS), 256>>>(ADLAV, HD, NTOK,
        lg,        NTOK, 1, (long long)HEADS * ADLAV * NTOK, (long long)ADLAV * NTOK,
        kv + DIMV, 2 * DIMV, 1, (long long)NTOK * 2 * DIMV, HD,
        av,        HD, 1, (long long)HEADS * ADLAV * HD, (long long)ADLAV * HD,
        nullptr, 0, 0, 0, 1.f);

    // 8. attn2 logits: [2744,48] @ [48,343] * SCALE + bias2^T
    sgemm<<<g2d(NTOK, ADLAV, BATCH * HEADS), 256>>>(NTOK, ADLAV, HD,
        q,    DIMV, 1, (long long)NTOK * DIMV, HD,
        adla, 1, DIMV, (long long)ADLAV * DIMV, HD,
        lg,   ADLAV, 1, (long long)HEADS * NTOK * ADLAV, (long long)NTOK * ADLAV,
        b2,   1, NTOK, (long long)ADLAV * NTOK,
        SCALEV);

    // 9. softmax rows over a (343)
    softmax_rows<<<BATCH * HEADS * NTOK, 128>>>(lg, ADLAV);

    // 10. out = P2 @ adla_v : [2744,343] @ [343,48] -> attnout[b,n,h*48+d]
    sgemm<<<g2d(NTOK, HD, BATCH * HEADS), 256>>>(NTOK, HD, ADLAV,
        lg, ADLAV, 1, (long long)HEADS * NTOK * ADLAV, (long long)NTOK * ADLAV,
        av, HD, 1, (long long)HEADS * ADLAV * HD, (long long)ADLAV * HD,
        ao, DIMV, 1, (long long)NTOK * DIMV, HD,
        nullptr, 0, 0, 0, 1.f);

    // 11. depthwise conv 3x3x3 of v, added into attnout
    {
        long long tot = (long long)BATCH * NTOK * DIMV;
        dwc_add<<<(unsigned)((tot + 255) / 256), 256>>>(kv, dwcw, dwcb, ao);
    }

    // 12. final: out = attnout @ Wproj + bproj
    sgemm<<<g2d(BN_TOT, DIMV, 1), 256>>>(BN_TOT, DIMV, DIMV,
        ao,    DIMV, 1, 0, 0,
        Wproj, DIMV, 1, 0, 0,
        out,   DIMV, 1, 0, 0,
        bproj, 0, 1, 0,
        1.f);

    (void)in_sizes; (void)n_in; (void)out_size;
}

// round 4
// speedup vs baseline: 1.9332x; 1.9332x over previous
#include <cuda_runtime.h>
#include <math.h>
#include <stdint.h>

#define HEADS   8
#define DIMV    384
#define HD      48
#define ADLAV   343
#define HWD     14
#define NTOK    2744
#define BATCH   8
#define SCALEV  0.14433756729740645f   // 48^-0.5

#define BN_TOT  (BATCH * NTOK)          // 21952

// ---------------- scratch (static device allocations; no cudaMalloc) --------
__device__ float g_q[BATCH * NTOK * DIMV];
__device__ float g_kv[BATCH * NTOK * 2 * DIMV];
__device__ float g_adla[BATCH * ADLAV * DIMV];
__device__ float g_bias1[HEADS * ADLAV * NTOK];
__device__ float g_bias2[HEADS * ADLAV * NTOK];     // [h,a,n]
__device__ float g_bias2t[HEADS * ADLAV * NTOK];    // [h,n,a]
__device__ float g_logits[BATCH * HEADS * ADLAV * NTOK];   // 241MB reused
__device__ float g_adlav[BATCH * HEADS * ADLAV * HD];
__device__ float g_attnout[BATCH * NTOK * DIMV];

// ---------------- tf32 helpers ----------------------------------------------
__device__ __forceinline__ uint32_t f2tf32(float x) {
    uint32_t r;
    asm("cvt.rna.tf32.f32 %0, %1;" : "=r"(r) : "f"(x));
    return r;
}

__device__ __forceinline__ void mma_tf32(float* c, const uint32_t* a, const uint32_t* b) {
    asm volatile(
        "mma.sync.aligned.m16n8k8.row.col.f32.tf32.tf32.f32 "
        "{%0,%1,%2,%3}, {%4,%5,%6,%7}, {%8,%9}, {%0,%1,%2,%3};\n"
        : "+f"(c[0]), "+f"(c[1]), "+f"(c[2]), "+f"(c[3])
        : "r"(a[0]), "r"(a[1]), "r"(a[2]), "r"(a[3]), "r"(b[0]), "r"(b[1]));
}

// ---------------- generic strided batched GEMM (tf32 tensor cores) -----------
// C[m,n] = alpha * sum_k A[m,k]*B[k,n]  (+ bias[m,n] if bias != null)
// batch z: b = z>>3, h = z&7.
// Tile 64x64, BK=16, 128 threads = 4 warps in 2x2, warp tile 32x32.
#define SMP 72   // smem row pitch (conflict-free fragment loads: 72 % 32 == 8)
__global__ __launch_bounds__(128) void tgemm(int M, int N, int K,
    const float* __restrict__ A, long long rsA, long long csA, long long bAb, long long bAh,
    const float* __restrict__ B, long long rsB, long long csB, long long bBb, long long bBh,
    float* __restrict__ C, long long rsC, long long csC, long long bCb, long long bCh,
    const float* __restrict__ Bi, long long rsBi, long long csBi, long long bBih,
    float alpha)
{
    __shared__ uint32_t As[16][SMP];
    __shared__ uint32_t Bs[16][SMP];

    int z  = blockIdx.z;
    int bb = z >> 3;
    int hh = z & 7;
    const float* Ab = A + (long long)bb * bAb + (long long)hh * bAh;
    const float* Bb = B + (long long)bb * bBb + (long long)hh * bBh;
    float*       Cb = C + (long long)bb * bCb + (long long)hh * bCh;
    const float* Bib = Bi ? (Bi + (long long)hh * bBih) : nullptr;

    int m0 = blockIdx.y * 64;
    int n0 = blockIdx.x * 64;
    int tid  = threadIdx.x;
    int warp = tid >> 5;
    int lane = tid & 31;
    int g  = lane >> 2;   // group 0..7
    int tg = lane & 3;    // thread-in-group 0..3
    int wm = warp & 1;    // warp m index (2)
    int wn = warp >> 1;   // warp n index (2)
    int mW = wm * 32;     // warp tile origin in block tile
    int nW = wn * 32;

    float acc[2][4][4];
    #pragma unroll
    for (int i = 0; i < 2; i++)
        #pragma unroll
        for (int j = 0; j < 4; j++)
            #pragma unroll
            for (int l = 0; l < 4; l++) acc[i][j][l] = 0.f;

    for (int k0 = 0; k0 < K; k0 += 16) {
        // fill As[kk][mm] and Bs[kk][nn] (tf32-rounded), guarded
        #pragma unroll
        for (int l = 0; l < 8; l++) {
            int idx = tid + l * 128;       // 0..1023
            int kk = idx >> 6;
            int mm = idx & 63;
            int k = k0 + kk;
            int m = m0 + mm;
            float av = (m < M && k < K) ? Ab[(long long)m * rsA + (long long)k * csA] : 0.f;
            As[kk][mm] = f2tf32(av);
            int n = n0 + mm;
            float bv = (n < N && k < K) ? Bb[(long long)k * rsB + (long long)n * csB] : 0.f;
            Bs[kk][mm] = f2tf32(bv);
        }
        __syncthreads();

        #pragma unroll
        for (int ks = 0; ks < 2; ks++) {
            int kk = ks * 8;
            uint32_t af[2][4];
            #pragma unroll
            for (int mi = 0; mi < 2; mi++) {
                int mb = mW + mi * 16;
                af[mi][0] = As[kk + tg][mb + g];
                af[mi][1] = As[kk + tg][mb + g + 8];
                af[mi][2] = As[kk + tg + 4][mb + g];
                af[mi][3] = As[kk + tg + 4][mb + g + 8];
            }
            uint32_t bf[4][2];
            #pragma unroll
            for (int ni = 0; ni < 4; ni++) {
                int nb = nW + ni * 8;
                bf[ni][0] = Bs[kk + tg][nb + g];
                bf[ni][1] = Bs[kk + tg + 4][nb + g];
            }
            #pragma unroll
            for (int mi = 0; mi < 2; mi++)
                #pragma unroll
                for (int ni = 0; ni < 4; ni++)
                    mma_tf32(acc[mi][ni], af[mi], bf[ni]);
        }
        __syncthreads();
    }

    // epilogue: c0:(g,2tg) c1:(g,2tg+1) c2:(g+8,2tg) c3:(g+8,2tg+1)
    #pragma unroll
    for (int mi = 0; mi < 2; mi++) {
        #pragma unroll
        for (int ni = 0; ni < 4; ni++) {
            #pragma unroll
            for (int l = 0; l < 4; l++) {
                int r = m0 + mW + mi * 16 + g + (l >> 1) * 8;
                int c = n0 + nW + ni * 8 + tg * 2 + (l & 1);
                if (r < M && c < N) {
                    float v = alpha * acc[mi][ni][l];
                    if (Bib) v += Bib[(long long)r * rsBi + (long long)c * csBi];
                    Cb[(long long)r * rsC + (long long)c * csC] = v;
                }
            }
        }
    }
}

// ---------------- pooling: adla[b,a,c] = mean over 2x2x2 of q ---------------
__global__ void pool_kernel(const float* __restrict__ q, float* __restrict__ adla)
{
    long long t = (long long)blockIdx.x * blockDim.x + threadIdx.x;
    if (t >= (long long)BATCH * ADLAV * DIMV) return;
    int c = (int)(t % DIMV);
    int a = (int)((t / DIMV) % ADLAV);
    int b = (int)(t / ((long long)DIMV * ADLAV));
    int p0 = a / 49, p1 = (a / 7) % 7, p2 = a % 7;
    float s = 0.f;
    #pragma unroll
    for (int r0 = 0; r0 < 2; r0++)
        #pragma unroll
        for (int r1 = 0; r1 < 2; r1++)
            #pragma unroll
            for (int r2 = 0; r2 < 2; r2++) {
                int i = p0 * 2 + r0, j = p1 * 2 + r1, k = p2 * 2 + r2;
                int n = (i * HWD + j) * HWD + k;
                s += q[((long long)b * NTOK + n) * DIMV + c];
            }
    adla[t] = s * 0.125f;
}

// ---------------- trilinear weights (7 -> 14) -------------------------------
__device__ __forceinline__ void lin_w(int o, int& x0, int& x1, float& w)
{
    float x = 0.5f * (float)o - 0.25f;
    x = fminf(fmaxf(x, 0.f), 6.f);
    x0 = (int)floorf(x);
    if (x0 > 6) x0 = 6;
    x1 = min(x0 + 1, 6);
    w = x - (float)x0;
}

// block per (h,a): stage 343-entry volumes in smem, write b1/b2 coalesced in n
__global__ void biasprep(const float* __restrict__ an, const float* __restrict__ na,
                         const float* __restrict__ ah, const float* __restrict__ aw,
                         const float* __restrict__ ad, const float* __restrict__ ha,
                         const float* __restrict__ wa, const float* __restrict__ da,
                         float* __restrict__ b1, float* __restrict__ b2)
{
    int haid = blockIdx.x;                 // 0 .. HEADS*ADLAV-1
    int h = haid / ADLAV;
    int a = haid % ADLAV;
    __shared__ float s_an[343], s_na[343];
    __shared__ float s_ax[3][14];          // ah/aw/ad for this (h,a)
    __shared__ float s_xa[3][14];          // ha/wa/da for this (h,a)
    int tid = threadIdx.x;
    const float* anb = an + (long long)haid * 343;
    const float* nab = na + (long long)haid * 343;
    for (int i = tid; i < 343; i += 256) { s_an[i] = anb[i]; s_na[i] = nab[i]; }
    if (tid < 14) {
        s_ax[0][tid] = ah[(long long)haid * HWD + tid];
        s_ax[1][tid] = aw[(long long)haid * HWD + tid];
        s_ax[2][tid] = ad[(long long)haid * HWD + tid];
        s_xa[0][tid] = ha[((long long)h * HWD + tid) * ADLAV + a];
        s_xa[1][tid] = wa[((long long)h * HWD + tid) * ADLAV + a];
        s_xa[2][tid] = da[((long long)h * HWD + tid) * ADLAV + a];
    }
    __syncthreads();
    long long base = (long long)haid * NTOK;
    for (int n = tid; n < NTOK; n += 256) {
        int i = n / (HWD * HWD), j = (n / HWD) % HWD, k = n % HWD;
        int i0, i1, j0, j1, k0, k1;
        float wi, wj, wk;
        lin_w(i, i0, i1, wi);
        lin_w(j, j0, j1, wj);
        lin_w(k, k0, k1, wk);
        float v1, v2;
        {
            const float* t = s_an;
            float c00 = (1.f-wk)*t[(i0*7+j0)*7+k0] + wk*t[(i0*7+j0)*7+k1];
            float c01 = (1.f-wk)*t[(i0*7+j1)*7+k0] + wk*t[(i0*7+j1)*7+k1];
            float c10 = (1.f-wk)*t[(i1*7+j0)*7+k0] + wk*t[(i1*7+j0)*7+k1];
            float c11 = (1.f-wk)*t[(i1*7+j1)*7+k0] + wk*t[(i1*7+j1)*7+k1];
            v1 = (1.f-wi)*((1.f-wj)*c00 + wj*c01) + wi*((1.f-wj)*c10 + wj*c11);
        }
        {
            const float* t = s_na;
            float c00 = (1.f-wk)*t[(i0*7+j0)*7+k0] + wk*t[(i0*7+j0)*7+k1];
            float c01 = (1.f-wk)*t[(i0*7+j1)*7+k0] + wk*t[(i0*7+j1)*7+k1];
            float c10 = (1.f-wk)*t[(i1*7+j0)*7+k0] + wk*t[(i1*7+j0)*7+k1];
            float c11 = (1.f-wk)*t[(i1*7+j1)*7+k0] + wk*t[(i1*7+j1)*7+k1];
            v2 = (1.f-wi)*((1.f-wj)*c00 + wj*c01) + wi*((1.f-wj)*c10 + wj*c11);
        }
        v1 += s_ax[0][i] + s_ax[1][j] + s_ax[2][k];
        v2 += s_xa[0][i] + s_xa[1][j] + s_xa[2][k];
        b1[base + n] = v1;
        b2[base + n] = v2;
    }
}

// tiled transpose: b2[h,a,n] -> b2t[h,n,a]
__global__ void transpose_b2(const float* __restrict__ b2, float* __restrict__ b2t)
{
    __shared__ float t[32][33];
    int h = blockIdx.z;
    int a0 = blockIdx.y * 32, n0 = blockIdx.x * 32;
    int x = threadIdx.x, y = threadIdx.y;   // 32 x 8
    #pragma unroll
    for (int yy = y; yy < 32; yy += 8) {
        int a = a0 + yy, n = n0 + x;
        if (a < ADLAV && n < NTOK)
            t[yy][x] = b2[((long long)h * ADLAV + a) * NTOK + n];
    }
    __syncthreads();
    #pragma unroll
    for (int yy = y; yy < 32; yy += 8) {
        int n = n0 + yy, a = a0 + x;
        if (a < ADLAV && n < NTOK)
            b2t[((long long)h * NTOK + n) * ADLAV + a] = t[x][yy];
    }
}

// ---------------- row softmax (in place) ------------------------------------
__global__ void softmax_rows(float* __restrict__ buf, int rowLen)
{
    float* p = buf + (long long)blockIdx.x * rowLen;
    __shared__ float red[128];
    int tid = threadIdx.x;
    float m = -1e30f;
    for (int i = tid; i < rowLen; i += 128) m = fmaxf(m, p[i]);
    red[tid] = m; __syncthreads();
    for (int s = 64; s > 0; s >>= 1) { if (tid < s) red[tid] = fmaxf(red[tid], red[tid + s]); __syncthreads(); }
    m = red[0]; __syncthreads();
    float sum = 0.f;
    for (int i = tid; i < rowLen; i += 128) {
        float e = __expf(p[i] - m);
        p[i] = e;
        sum += e;
    }
    red[tid] = sum; __syncthreads();
    for (int s = 64; s > 0; s >>= 1) { if (tid < s) red[tid] += red[tid + s]; __syncthreads(); }
    float inv = 1.f / red[0];
    for (int i = tid; i < rowLen; i += 128) p[i] *= inv;
}

// ---------------- depthwise 3x3x3 conv (SAME), add into out -----------------
__global__ void dwc_add(const float* __restrict__ kv, const float* __restrict__ w,
                        const float* __restrict__ bvec, float* __restrict__ out)
{
    long long t = (long long)blockIdx.x * blockDim.x + threadIdx.x;
    if (t >= (long long)BATCH * NTOK * DIMV) return;
    int c = (int)(t % DIMV);
    int n = (int)((t / DIMV) % NTOK);
    int b = (int)(t / ((long long)DIMV * NTOK));
    int i = n / (HWD * HWD), j = (n / HWD) % HWD, k = n % HWD;
    float acc = bvec[c];
    const float* wc = w + (long long)c * 27;
    #pragma unroll
    for (int di = -1; di <= 1; di++) {
        int ii = i + di;
        if (ii < 0 || ii >= HWD) continue;
        #pragma unroll
        for (int dj = -1; dj <= 1; dj++) {
            int jj = j + dj;
            if (jj < 0 || jj >= HWD) continue;
            #pragma unroll
            for (int dk = -1; dk <= 1; dk++) {
                int kk = k + dk;
                if (kk < 0 || kk >= HWD) continue;
                int nn = (ii * HWD + jj) * HWD + kk;
                acc += kv[((long long)b * NTOK + nn) * (2 * DIMV) + DIMV + c]
                     * wc[(di + 1) * 9 + (dj + 1) * 3 + (dk + 1)];
            }
        }
    }
    out[t] += acc;
}

// ---------------- host launcher ---------------------------------------------
static inline dim3 g2d(int M, int N, int Z) {
    return dim3((unsigned)((N + 63) / 64), (unsigned)((M + 63) / 64), (unsigned)Z);
}

extern "C" void kernel_launch(void* const* d_in, const int* in_sizes, int n_in,
                              void* d_out, int out_size)
{
    const float* x     = (const float*)d_in[0];
    const float* Wq    = (const float*)d_in[1];
    const float* Wkv   = (const float*)d_in[2];
    const float* Wproj = (const float*)d_in[3];
    const float* bproj = (const float*)d_in[4];
    const float* dwcw  = (const float*)d_in[5];
    const float* dwcb  = (const float*)d_in[6];
    const float* an    = (const float*)d_in[7];
    const float* na    = (const float*)d_in[8];
    const float* ah    = (const float*)d_in[9];
    const float* aw    = (const float*)d_in[10];
    const float* ad    = (const float*)d_in[11];
    const float* ha    = (const float*)d_in[12];
    const float* wa    = (const float*)d_in[13];
    const float* da    = (const float*)d_in[14];
    float* out = (float*)d_out;

    void *pq, *pkv, *padla, *pb1, *pb2, *pb2t, *plog, *pav, *pao;
    cudaGetSymbolAddress(&pq, g_q);
    cudaGetSymbolAddress(&pkv, g_kv);
    cudaGetSymbolAddress(&padla, g_adla);
    cudaGetSymbolAddress(&pb1, g_bias1);
    cudaGetSymbolAddress(&pb2, g_bias2);
    cudaGetSymbolAddress(&pb2t, g_bias2t);
    cudaGetSymbolAddress(&plog, g_logits);
    cudaGetSymbolAddress(&pav, g_adlav);
    cudaGetSymbolAddress(&pao, g_attnout);
    float* q    = (float*)pq;
    float* kv   = (float*)pkv;
    float* adla = (float*)padla;
    float* b1   = (float*)pb1;
    float* b2   = (float*)pb2;
    float* b2t  = (float*)pb2t;
    float* lg   = (float*)plog;
    float* av   = (float*)pav;
    float* ao   = (float*)pao;

    // 1. q = x @ Wq
    tgemm<<<g2d(BN_TOT, DIMV, 1), 128>>>(BN_TOT, DIMV, DIMV,
        x,  DIMV, 1, 0, 0,
        Wq, DIMV, 1, 0, 0,
        q,  DIMV, 1, 0, 0,
        nullptr, 0, 0, 0, 1.f);

    // 2. kv = x @ Wkv
    tgemm<<<g2d(BN_TOT, 2 * DIMV, 1), 128>>>(BN_TOT, 2 * DIMV, DIMV,
        x,   DIMV,    1, 0, 0,
        Wkv, 2 * DIMV, 1, 0, 0,
        kv,  2 * DIMV, 1, 0, 0,
        nullptr, 0, 0, 0, 1.f);

    // 3. adla pooling
    {
        long long tot = (long long)BATCH * ADLAV * DIMV;
        pool_kernel<<<(unsigned)((tot + 255) / 256), 256>>>(q, adla);
    }

    // 4. bias tables + transpose
    biasprep<<<HEADS * ADLAV, 256>>>(an, na, ah, aw, ad, ha, wa, da, b1, b2);
    transpose_b2<<<dim3((NTOK + 31) / 32, (ADLAV + 31) / 32, HEADS), dim3(32, 8)>>>(b2, b2t);

    // 5. attn1 logits: [343,2744] = [343,48] @ [48,2744] * SCALE + bias1
    tgemm<<<g2d(ADLAV, NTOK, BATCH * HEADS), 128>>>(ADLAV, NTOK, HD,
        adla, DIMV, 1, (long long)ADLAV * DIMV, HD,
        kv,   1, 2 * DIMV, (long long)NTOK * 2 * DIMV, HD,
        lg,   NTOK, 1, (long long)HEADS * ADLAV * NTOK, (long long)ADLAV * NTOK,
        b1,   NTOK, 1, (long long)ADLAV * NTOK,
        SCALEV);

    // 6. softmax rows over n (2744)
    softmax_rows<<<BATCH * HEADS * ADLAV, 128>>>(lg, NTOK);

    // 7. adla_v = P1 @ V : [343,2744] @ [2744,48]
    tgemm<<<g2d(ADLAV, HD, BATCH * HEADS), 128>>>(ADLAV, HD, NTOK,
        lg,        NTOK, 1, (long long)HEADS * ADLAV * NTOK, (long long)ADLAV * NTOK,
        kv + DIMV, 2 * DIMV, 1, (long long)NTOK * 2 * DIMV, HD,
        av,        HD, 1, (long long)HEADS * ADLAV * HD, (long long)ADLAV * HD,
        nullptr, 0, 0, 0, 1.f);

    // 8. attn2 logits: [2744,343] = [2744,48] @ [48,343] * SCALE + bias2t
    tgemm<<<g2d(NTOK, ADLAV, BATCH * HEADS), 128>>>(NTOK, ADLAV, HD,
        q,    DIMV, 1, (long long)NTOK * DIMV, HD,
        adla, 1, DIMV, (long long)ADLAV * DIMV, HD,
        lg,   ADLAV, 1, (long long)HEADS * NTOK * ADLAV, (long long)NTOK * ADLAV,
        b2t,  ADLAV, 1, (long long)NTOK * ADLAV,
        SCALEV);

    // 9. softmax rows over a (343)
    softmax_rows<<<BATCH * HEADS * NTOK, 128>>>(lg, ADLAV);

    // 10. out = P2 @ adla_v : [2744,343] @ [343,48]
    tgemm<<<g2d(NTOK, HD, BATCH * HEADS), 128>>>(NTOK, HD, ADLAV,
        lg, ADLAV, 1, (long long)HEADS * NTOK * ADLAV, (long long)NTOK * ADLAV,
        av, HD, 1, (long long)HEADS * ADLAV * HD, (long long)ADLAV * HD,
        ao, DIMV, 1, (long long)NTOK * DIMV, HD,
        nullptr, 0, 0, 0, 1.f);

    // 11. depthwise conv 3x3x3 of v, added into attnout
    {
        long long tot = (long long)BATCH * NTOK * DIMV;
        dwc_add<<<(unsigned)((tot + 255) / 256), 256>>>(kv, dwcw, dwcb, ao);
    }

    // 12. final: out = attnout @ Wproj + bproj
    tgemm<<<g2d(BN_TOT, DIMV, 1), 128>>>(BN_TOT, DIMV, DIMV,
        ao,    DIMV, 1, 0, 0,
        Wproj, DIMV, 1, 0, 0,
        out,   DIMV, 1, 0, 0,
        bproj, 0, 1, 0,
        1.f);

    (void)in_sizes; (void)n_in; (void)out_size;
}

// round 5
// speedup vs baseline: 3.2069x; 1.6588x over previous
#include <cuda_runtime.h>
#include <math.h>
#include <stdint.h>

#define HEADS   8
#define DIMV    384
#define HD      48
#define ADLAV   343
#define HWD     14
#define NTOK    2744
#define BATCH   8
#define SCALEV  0.14433756729740645f   // 48^-0.5
#define LG2PAD  352                    // padded row stride for attn2 logits

#define BN_TOT  (BATCH * NTOK)         // 21952

// ---------------- scratch (static device allocations) ------------------------
__device__ float g_q[BATCH * NTOK * DIMV];
__device__ float g_kv[BATCH * NTOK * 2 * DIMV];
__device__ float g_adla[BATCH * ADLAV * DIMV];
__device__ float g_bias1[HEADS * ADLAV * NTOK];
__device__ float g_bias2[HEADS * ADLAV * NTOK];      // [h,a,n]
__device__ float g_bias2t[HEADS * ADLAV * NTOK];     // [h,n,a]
__device__ float g_logits[BATCH * HEADS * NTOK * LG2PAD];  // 247MB, reused
__device__ float g_adlav[BATCH * HEADS * ADLAV * HD];
__device__ float g_attnout[BATCH * NTOK * DIMV];

// ---------------- tf32 helpers ----------------------------------------------
__device__ __forceinline__ uint32_t f2tf32(float x) {
    uint32_t r;
    asm("cvt.rna.tf32.f32 %0, %1;" : "=r"(r) : "f"(x));
    return r;
}

__device__ __forceinline__ void mma_tf32(float* c, const uint32_t* a, const uint32_t* b) {
    asm volatile(
        "mma.sync.aligned.m16n8k8.row.col.f32.tf32.tf32.f32 "
        "{%0,%1,%2,%3}, {%4,%5,%6,%7}, {%8,%9}, {%0,%1,%2,%3};\n"
        : "+f"(c[0]), "+f"(c[1]), "+f"(c[2]), "+f"(c[3])
        : "r"(a[0]), "r"(a[1]), "r"(a[2]), "r"(a[3]), "r"(b[0]), "r"(b[1]));
}

// ---------------- generic strided batched GEMM (tf32 tensor cores) -----------
// C[m,n] = alpha * sum_k A[m,k]*B[k,n]  (+ bias if Bi != null)
// Tile 128x64, BK=16, 256 threads = 8 warps (4 m x 2 n), warp tile 32x32.
// Double-buffered smem, register prefetch, 1 syncthreads per k-step.
#define BMT 128
#define BNT 64
#define BKT 16
#define PA 136
#define PB 72
__global__ __launch_bounds__(256) void tgemm(int M, int N, int K,
    const float* __restrict__ A, long long rsA, long long csA, long long bAb, long long bAh,
    const float* __restrict__ B, long long rsB, long long csB, long long bBb, long long bBh,
    float* __restrict__ C, long long rsC, long long csC, long long bCb, long long bCh,
    const float* __restrict__ Bi, long long rsBi, long long csBi, long long bBih,
    float alpha)
{
    __shared__ uint32_t As[2][BKT][PA];
    __shared__ uint32_t Bs[2][BKT][PB];

    int z  = blockIdx.z;
    int bb = z >> 3;
    int hh = z & 7;
    const float* Ab = A + (long long)bb * bAb + (long long)hh * bAh;
    const float* Bb = B + (long long)bb * bBb + (long long)hh * bBh;
    float*       Cb = C + (long long)bb * bCb + (long long)hh * bCh;
    const float* Bib = Bi ? (Bi + (long long)hh * bBih) : nullptr;

    int m0 = blockIdx.y * BMT;
    int n0 = blockIdx.x * BNT;
    int tid  = threadIdx.x;
    int warp = tid >> 5;
    int lane = tid & 31;
    int g  = lane >> 2;
    int tg = lane & 3;
    int wm = warp & 3;
    int wn = warp >> 2;
    int mW = wm * 32;
    int nW = wn * 32;

    // A fill coords: m = tid&127, kq = tid>>7 (+2 for second)
    int amM = tid & 127;
    int akq = tid >> 7;
    // B contiguous-n coords
    int bnKK = tid >> 4;
    int bnNQ = tid & 15;
    // B contiguous-k coords
    int bkN  = tid & 63;
    int bkKQ = tid >> 6;
    const bool bContigN = (csB == 1);

    float acc[2][4][4];
    #pragma unroll
    for (int i = 0; i < 2; i++)
        #pragma unroll
        for (int j = 0; j < 4; j++)
            #pragma unroll
            for (int l = 0; l < 4; l++) acc[i][j][l] = 0.f;

    float4 va[2], vb;

    // ---- load tile (k0) into registers ----
    auto loadTile = [&](int k0) {
        #pragma unroll
        for (int i = 0; i < 2; i++) {
            int kq = akq + i * 2;
            int gm = m0 + amM, gk = k0 + kq * 4;
            float4 v = make_float4(0.f, 0.f, 0.f, 0.f);
            if (gm < M) {
                if (csA == 1 && gk + 4 <= K) {
                    v = *(const float4*)(Ab + (long long)gm * rsA + gk);
                } else {
                    float* pv = (float*)&v;
                    #pragma unroll
                    for (int j = 0; j < 4; j++)
                        if (gk + j < K) pv[j] = Ab[(long long)gm * rsA + (long long)(gk + j) * csA];
                }
            }
            va[i] = v;
        }
        float4 v = make_float4(0.f, 0.f, 0.f, 0.f);
        if (bContigN) {
            int gk = k0 + bnKK, gn = n0 + bnNQ * 4;
            if (gk < K) {
                if (gn + 4 <= N) {
                    v = *(const float4*)(Bb + (long long)gk * rsB + gn);
                } else {
                    float* pv = (float*)&v;
                    #pragma unroll
                    for (int j = 0; j < 4; j++)
                        if (gn + j < N) pv[j] = Bb[(long long)gk * rsB + (long long)(gn + j)];
                }
            }
        } else {
            int gn = n0 + bkN, gk = k0 + bkKQ * 4;
            if (gn < N) {
                if (rsB == 1 && gk + 4 <= K) {
                    v = *(const float4*)(Bb + (long long)gn * csB + gk);
                } else {
                    float* pv = (float*)&v;
                    #pragma unroll
                    for (int j = 0; j < 4; j++)
                        if (gk + j < K) pv[j] = Bb[(long long)(gk + j) * rsB + (long long)gn * csB];
                }
            }
        }
        vb = v;
    };

    // ---- store registers -> smem buffer ----
    auto storeTile = [&](int bsel) {
        #pragma unroll
        for (int i = 0; i < 2; i++) {
            int kq = akq + i * 2;
            const float* pv = (const float*)&va[i];
            #pragma unroll
            for (int j = 0; j < 4; j++)
                As[bsel][kq * 4 + j][amM] = f2tf32(pv[j]);
        }
        const float* pv = (const float*)&vb;
        if (bContigN) {
            uint4 u;
            u.x = f2tf32(pv[0]); u.y = f2tf32(pv[1]);
            u.z = f2tf32(pv[2]); u.w = f2tf32(pv[3]);
            *(uint4*)&Bs[bsel][bnKK][bnNQ * 4] = u;
        } else {
            #pragma unroll
            for (int j = 0; j < 4; j++)
                Bs[bsel][bkKQ * 4 + j][bkN] = f2tf32(pv[j]);
        }
    };

    // ---- compute on smem buffer ----
    auto compute = [&](int bsel) {
        #pragma unroll
        for (int ks = 0; ks < 2; ks++) {
            int kk = ks * 8;
            uint32_t af[2][4];
            #pragma unroll
            for (int mi = 0; mi < 2; mi++) {
                int mb = mW + mi * 16;
                af[mi][0] = As[bsel][kk + tg][mb + g];
                af[mi][1] = As[bsel][kk + tg][mb + g + 8];
                af[mi][2] = As[bsel][kk + tg + 4][mb + g];
                af[mi][3] = As[bsel][kk + tg + 4][mb + g + 8];
            }
            uint32_t bf[4][2];
            #pragma unroll
            for (int ni = 0; ni < 4; ni++) {
                int nb = nW + ni * 8;
                bf[ni][0] = Bs[bsel][kk + tg][nb + g];
                bf[ni][1] = Bs[bsel][kk + tg + 4][nb + g];
            }
            #pragma unroll
            for (int mi = 0; mi < 2; mi++)
                #pragma unroll
                for (int ni = 0; ni < 4; ni++)
                    mma_tf32(acc[mi][ni], af[mi], bf[ni]);
        }
    };

    int nk = (K + BKT - 1) / BKT;
    loadTile(0);
    storeTile(0);
    __syncthreads();
    int buf = 0;
    for (int i = 0; i < nk; i++) {
        if (i + 1 < nk) loadTile((i + 1) * BKT);
        compute(buf);
        if (i + 1 < nk) {
            storeTile(buf ^ 1);
            buf ^= 1;
            __syncthreads();
        }
    }

    // ---- epilogue ----
    bool vecC = (csC == 1) && ((rsC & 1) == 0);
    #pragma unroll
    for (int mi = 0; mi < 2; mi++) {
        #pragma unroll
        for (int ni = 0; ni < 4; ni++) {
            #pragma unroll
            for (int half = 0; half < 2; half++) {
                int r = m0 + mW + mi * 16 + g + half * 8;
                if (r >= M) continue;
                int c = n0 + nW + ni * 8 + tg * 2;
                float v0 = alpha * acc[mi][ni][half * 2];
                float v1 = alpha * acc[mi][ni][half * 2 + 1];
                if (Bib) {
                    if (c < N)     v0 += Bib[(long long)r * rsBi + (long long)c * csBi];
                    if (c + 1 < N) v1 += Bib[(long long)r * rsBi + (long long)(c + 1) * csBi];
                }
                if (vecC && c + 2 <= N) {
                    float2 w; w.x = v0; w.y = v1;
                    *(float2*)(Cb + (long long)r * rsC + c) = w;
                } else {
                    if (c < N)     Cb[(long long)r * rsC + (long long)c * csC] = v0;
                    if (c + 1 < N) Cb[(long long)r * rsC + (long long)(c + 1) * csC] = v1;
                }
            }
        }
    }
}

// ---------------- pooling ----------------------------------------------------
__global__ void pool_kernel(const float* __restrict__ q, float* __restrict__ adla)
{
    long long t = (long long)blockIdx.x * blockDim.x + threadIdx.x;
    if (t >= (long long)BATCH * ADLAV * DIMV) return;
    int c = (int)(t % DIMV);
    int a = (int)((t / DIMV) % ADLAV);
    int b = (int)(t / ((long long)DIMV * ADLAV));
    int p0 = a / 49, p1 = (a / 7) % 7, p2 = a % 7;
    float s = 0.f;
    #pragma unroll
    for (int r0 = 0; r0 < 2; r0++)
        #pragma unroll
        for (int r1 = 0; r1 < 2; r1++)
            #pragma unroll
            for (int r2 = 0; r2 < 2; r2++) {
                int i = p0 * 2 + r0, j = p1 * 2 + r1, k = p2 * 2 + r2;
                int n = (i * HWD + j) * HWD + k;
                s += q[((long long)b * NTOK + n) * DIMV + c];
            }
    adla[t] = s * 0.125f;
}

// ---------------- trilinear weights (7 -> 14) --------------------------------
__device__ __forceinline__ void lin_w(int o, int& x0, int& x1, float& w)
{
    float x = 0.5f * (float)o - 0.25f;
    x = fminf(fmaxf(x, 0.f), 6.f);
    x0 = (int)floorf(x);
    if (x0 > 6) x0 = 6;
    x1 = min(x0 + 1, 6);
    w = x - (float)x0;
}

__global__ void biasprep(const float* __restrict__ an, const float* __restrict__ na,
                         const float* __restrict__ ah, const float* __restrict__ aw,
                         const float* __restrict__ ad, const float* __restrict__ ha,
                         const float* __restrict__ wa, const float* __restrict__ da,
                         float* __restrict__ b1, float* __restrict__ b2)
{
    int haid = blockIdx.x;
    int h = haid / ADLAV;
    int a = haid % ADLAV;
    __shared__ float s_an[343], s_na[343];
    __shared__ float s_ax[3][14];
    __shared__ float s_xa[3][14];
    int tid = threadIdx.x;
    const float* anb = an + (long long)haid * 343;
    const float* nab = na + (long long)haid * 343;
    for (int i = tid; i < 343; i += 256) { s_an[i] = anb[i]; s_na[i] = nab[i]; }
    if (tid < 14) {
        s_ax[0][tid] = ah[(long long)haid * HWD + tid];
        s_ax[1][tid] = aw[(long long)haid * HWD + tid];
        s_ax[2][tid] = ad[(long long)haid * HWD + tid];
        s_xa[0][tid] = ha[((long long)h * HWD + tid) * ADLAV + a];
        s_xa[1][tid] = wa[((long long)h * HWD + tid) * ADLAV + a];
        s_xa[2][tid] = da[((long long)h * HWD + tid) * ADLAV + a];
    }
    __syncthreads();
    long long base = (long long)haid * NTOK;
    for (int n = tid; n < NTOK; n += 256) {
        int i = n / (HWD * HWD), j = (n / HWD) % HWD, k = n % HWD;
        int i0, i1, j0, j1, k0, k1;
        float wi, wj, wk;
        lin_w(i, i0, i1, wi);
        lin_w(j, j0, j1, wj);
        lin_w(k, k0, k1, wk);
        float v1, v2;
        {
            const float* t = s_an;
            float c00 = (1.f-wk)*t[(i0*7+j0)*7+k0] + wk*t[(i0*7+j0)*7+k1];
            float c01 = (1.f-wk)*t[(i0*7+j1)*7+k0] + wk*t[(i0*7+j1)*7+k1];
            float c10 = (1.f-wk)*t[(i1*7+j0)*7+k0] + wk*t[(i1*7+j0)*7+k1];
            float c11 = (1.f-wk)*t[(i1*7+j1)*7+k0] + wk*t[(i1*7+j1)*7+k1];
            v1 = (1.f-wi)*((1.f-wj)*c00 + wj*c01) + wi*((1.f-wj)*c10 + wj*c11);
        }
        {
            const float* t = s_na;
            float c00 = (1.f-wk)*t[(i0*7+j0)*7+k0] + wk*t[(i0*7+j0)*7+k1];
            float c01 = (1.f-wk)*t[(i0*7+j1)*7+k0] + wk*t[(i0*7+j1)*7+k1];
            float c10 = (1.f-wk)*t[(i1*7+j0)*7+k0] + wk*t[(i1*7+j0)*7+k1];
            float c11 = (1.f-wk)*t[(i1*7+j1)*7+k0] + wk*t[(i1*7+j1)*7+k1];
            v2 = (1.f-wi)*((1.f-wj)*c00 + wj*c01) + wi*((1.f-wj)*c10 + wj*c11);
        }
        v1 += s_ax[0][i] + s_ax[1][j] + s_ax[2][k];
        v2 += s_xa[0][i] + s_xa[1][j] + s_xa[2][k];
        b1[base + n] = v1;
        b2[base + n] = v2;
    }
}

// tiled transpose: b2[h,a,n] -> b2t[h,n,a]
__global__ void transpose_b2(const float* __restrict__ b2, float* __restrict__ b2t)
{
    __shared__ float t[32][33];
    int h = blockIdx.z;
    int a0 = blockIdx.y * 32, n0 = blockIdx.x * 32;
    int x = threadIdx.x, y = threadIdx.y;
    #pragma unroll
    for (int yy = y; yy < 32; yy += 8) {
        int a = a0 + yy, n = n0 + x;
        if (a < ADLAV && n < NTOK)
            t[yy][x] = b2[((long long)h * ADLAV + a) * NTOK + n];
    }
    __syncthreads();
    #pragma unroll
    for (int yy = y; yy < 32; yy += 8) {
        int n = n0 + yy, a = a0 + x;
        if (a < ADLAV && n < NTOK)
            b2t[((long long)h * NTOK + n) * ADLAV + a] = t[x][yy];
    }
}

// ---------------- block softmax (long rows, in place) ------------------------
__global__ void softmax_rows(float* __restrict__ buf, int rowLen, int rowStride)
{
    float* p = buf + (long long)blockIdx.x * rowStride;
    __shared__ float red[128];
    int tid = threadIdx.x;
    float m = -1e30f;
    for (int i = tid; i < rowLen; i += 128) m = fmaxf(m, p[i]);
    red[tid] = m; __syncthreads();
    for (int s = 64; s > 0; s >>= 1) { if (tid < s) red[tid] = fmaxf(red[tid], red[tid + s]); __syncthreads(); }
    m = red[0]; __syncthreads();
    float sum = 0.f;
    for (int i = tid; i < rowLen; i += 128) {
        float e = __expf(p[i] - m);
        p[i] = e;
        sum += e;
    }
    red[tid] = sum; __syncthreads();
    for (int s = 64; s > 0; s >>= 1) { if (tid < s) red[tid] += red[tid + s]; __syncthreads(); }
    float inv = 1.f / red[0];
    for (int i = tid; i < rowLen; i += 128) p[i] *= inv;
}

// ---------------- warp softmax (rowLen=343, register-resident) ---------------
__global__ void softmax_warp343(float* __restrict__ buf, int rows, int rowStride)
{
    int w = (int)((blockIdx.x * (long long)blockDim.x + threadIdx.x) >> 5);
    if (w >= rows) return;
    int lane = threadIdx.x & 31;
    float* p = buf + (long long)w * rowStride;
    float vals[11];
    float m = -1e30f;
    #pragma unroll
    for (int i = 0; i < 11; i++) {
        int idx = lane + i * 32;
        vals[i] = (idx < ADLAV) ? p[idx] : -1e30f;
        m = fmaxf(m, vals[i]);
    }
    #pragma unroll
    for (int s = 16; s > 0; s >>= 1) m = fmaxf(m, __shfl_xor_sync(0xffffffffu, m, s));
    float sum = 0.f;
    #pragma unroll
    for (int i = 0; i < 11; i++) {
        float e = __expf(vals[i] - m);
        vals[i] = e;
        sum += e;
    }
    #pragma unroll
    for (int s = 16; s > 0; s >>= 1) sum += __shfl_xor_sync(0xffffffffu, sum, s);
    float inv = 1.f / sum;
    #pragma unroll
    for (int i = 0; i < 11; i++) {
        int idx = lane + i * 32;
        if (idx < ADLAV) p[idx] = vals[i] * inv;
    }
}

// ---------------- depthwise 3x3x3 conv (SAME), add into out ------------------
__global__ void dwc_add(const float* __restrict__ kv, const float* __restrict__ w,
                        const float* __restrict__ bvec, float* __restrict__ out)
{
    long long t = (long long)blockIdx.x * blockDim.x + threadIdx.x;
    if (t >= (long long)BATCH * NTOK * DIMV) return;
    int c = (int)(t % DIMV);
    int n = (int)((t / DIMV) % NTOK);
    int b = (int)(t / ((long long)DIMV * NTOK));
    int i = n / (HWD * HWD), j = (n / HWD) % HWD, k = n % HWD;
    float acc = bvec[c];
    const float* wc = w + (long long)c * 27;
    #pragma unroll
    for (int di = -1; di <= 1; di++) {
        int ii = i + di;
        if (ii < 0 || ii >= HWD) continue;
        #pragma unroll
        for (int dj = -1; dj <= 1; dj++) {
            int jj = j + dj;
            if (jj < 0 || jj >= HWD) continue;
            #pragma unroll
            for (int dk = -1; dk <= 1; dk++) {
                int kk = k + dk;
                if (kk < 0 || kk >= HWD) continue;
                int nn = (ii * HWD + jj) * HWD + kk;
                acc += kv[((long long)b * NTOK + nn) * (2 * DIMV) + DIMV + c]
                     * wc[(di + 1) * 9 + (dj + 1) * 3 + (dk + 1)];
            }
        }
    }
    out[t] += acc;
}

// ---------------- host launcher ----------------------------------------------
static inline dim3 gT(int M, int N, int Z) {
    return dim3((unsigned)((N + BNT - 1) / BNT), (unsigned)((M + BMT - 1) / BMT), (unsigned)Z);
}

extern "C" void kernel_launch(void* const* d_in, const int* in_sizes, int n_in,
                              void* d_out, int out_size)
{
    const float* x     = (const float*)d_in[0];
    const float* Wq    = (const float*)d_in[1];
    const float* Wkv   = (const float*)d_in[2];
    const float* Wproj = (const float*)d_in[3];
    const float* bproj = (const float*)d_in[4];
    const float* dwcw  = (const float*)d_in[5];
    const float* dwcb  = (const float*)d_in[6];
    const float* an    = (const float*)d_in[7];
    const float* na    = (const float*)d_in[8];
    const float* ah    = (const float*)d_in[9];
    const float* aw    = (const float*)d_in[10];
    const float* ad    = (const float*)d_in[11];
    const float* ha    = (const float*)d_in[12];
    const float* wa    = (const float*)d_in[13];
    const float* da    = (const float*)d_in[14];
    float* out = (float*)d_out;

    void *pq, *pkv, *padla, *pb1, *pb2, *pb2t, *plog, *pav, *pao;
    cudaGetSymbolAddress(&pq, g_q);
    cudaGetSymbolAddress(&pkv, g_kv);
    cudaGetSymbolAddress(&padla, g_adla);
    cudaGetSymbolAddress(&pb1, g_bias1);
    cudaGetSymbolAddress(&pb2, g_bias2);
    cudaGetSymbolAddress(&pb2t, g_bias2t);
    cudaGetSymbolAddress(&plog, g_logits);
    cudaGetSymbolAddress(&pav, g_adlav);
    cudaGetSymbolAddress(&pao, g_attnout);
    float* q    = (float*)pq;
    float* kv   = (float*)pkv;
    float* adla = (float*)padla;
    float* b1   = (float*)pb1;
    float* b2   = (float*)pb2;
    float* b2t  = (float*)pb2t;
    float* lg   = (float*)plog;
    float* av   = (float*)pav;
    float* ao   = (float*)pao;

    // 1. q = x @ Wq
    tgemm<<<gT(BN_TOT, DIMV, 1), 256>>>(BN_TOT, DIMV, DIMV,
        x,  DIMV, 1, 0, 0,
        Wq, DIMV, 1, 0, 0,
        q,  DIMV, 1, 0, 0,
        nullptr, 0, 0, 0, 1.f);

    // 2. kv = x @ Wkv
    tgemm<<<gT(BN_TOT, 2 * DIMV, 1), 256>>>(BN_TOT, 2 * DIMV, DIMV,
        x,   DIMV,    1, 0, 0,
        Wkv, 2 * DIMV, 1, 0, 0,
        kv,  2 * DIMV, 1, 0, 0,
        nullptr, 0, 0, 0, 1.f);

    // 3. adla pooling
    {
        long long tot = (long long)BATCH * ADLAV * DIMV;
        pool_kernel<<<(unsigned)((tot + 255) / 256), 256>>>(q, adla);
    }

    // 4. bias tables + transpose
    biasprep<<<HEADS * ADLAV, 256>>>(an, na, ah, aw, ad, ha, wa, da, b1, b2);
    transpose_b2<<<dim3((NTOK + 31) / 32, (ADLAV + 31) / 32, HEADS), dim3(32, 8)>>>(b2, b2t);

    // 5. attn1 logits: [343,2744] = [343,48] @ [48,2744] * SCALE + bias1 (row stride NTOK)
    tgemm<<<gT(ADLAV, NTOK, BATCH * HEADS), 256>>>(ADLAV, NTOK, HD,
        adla, DIMV, 1, (long long)ADLAV * DIMV, HD,
        kv,   1, 2 * DIMV, (long long)NTOK * 2 * DIMV, HD,
        lg,   NTOK, 1, (long long)HEADS * ADLAV * NTOK, (long long)ADLAV * NTOK,
        b1,   NTOK, 1, (long long)ADLAV * NTOK,
        SCALEV);

    // 6. softmax rows over n (2744)
    softmax_rows<<<BATCH * HEADS * ADLAV, 128>>>(lg, NTOK, NTOK);

    // 7. adla_v = P1 @ V : [343,2744] @ [2744,48]
    tgemm<<<gT(ADLAV, HD, BATCH * HEADS), 256>>>(ADLAV, HD, NTOK,
        lg,        NTOK, 1, (long long)HEADS * ADLAV * NTOK, (long long)ADLAV * NTOK,
        kv + DIMV, 2 * DIMV, 1, (long long)NTOK * 2 * DIMV, HD,
        av,        HD, 1, (long long)HEADS * ADLAV * HD, (long long)ADLAV * HD,
        nullptr, 0, 0, 0, 1.f);

    // 8. attn2 logits: [2744,343] = [2744,48] @ [48,343] * SCALE + bias2t (PADDED row stride)
    tgemm<<<gT(NTOK, ADLAV, BATCH * HEADS), 256>>>(NTOK, ADLAV, HD,
        q,    DIMV, 1, (long long)NTOK * DIMV, HD,
        adla, 1, DIMV, (long long)ADLAV * DIMV, HD,
        lg,   LG2PAD, 1, (long long)HEADS * NTOK * LG2PAD, (long long)NTOK * LG2PAD,
        b2t,  ADLAV, 1, (long long)NTOK * ADLAV,
        SCALEV);

    // 9. softmax rows over a (343) — warp per row
    {
        int rows = BATCH * HEADS * NTOK;
        int blocks = (rows * 32 + 255) / 256;
        softmax_warp343<<<blocks, 256>>>(lg, rows, LG2PAD);
    }

    // 10. out = P2 @ adla_v : [2744,343] @ [343,48]
    tgemm<<<gT(NTOK, HD, BATCH * HEADS), 256>>>(NTOK, HD, ADLAV,
        lg, LG2PAD, 1, (long long)HEADS * NTOK * LG2PAD, (long long)NTOK * LG2PAD,
        av, HD, 1, (long long)HEADS * ADLAV * HD, (long long)ADLAV * HD,
        ao, DIMV, 1, (long long)NTOK * DIMV, HD,
        nullptr, 0, 0, 0, 1.f);

    // 11. depthwise conv 3x3x3 of v, added into attnout
    {
        long long tot = (long long)BATCH * NTOK * DIMV;
        dwc_add<<<(unsigned)((tot + 255) / 256), 256>>>(kv, dwcw, dwcb, ao);
    }

    // 12. final: out = attnout @ Wproj + bproj
    tgemm<<<gT(BN_TOT, DIMV, 1), 256>>>(BN_TOT, DIMV, DIMV,
        ao,    DIMV, 1, 0, 0,
        Wproj, DIMV, 1, 0, 0,
        out,   DIMV, 1, 0, 0,
        bproj, 0, 1, 0,
        1.f);

    (void)in_sizes; (void)n_in; (void)out_size;
}